// round 2
// baseline (speedup 1.0000x reference)
#include <cuda_runtime.h>
#include <cstddef>

// Problem constants (from reference_code)
#define D_DIM   64
#define N_USERS 4096
#define N_ITEMS 16384
#define L_U     50
#define L_I     20
#define OUT_W   (D_DIM + 2)   // 66

// One warp per row. Lane l owns columns 2l, 2l+1.
// IS_USER: P row = [s(64), bi.h1 + sum_w + bias, 1]
// item:    Q row = [s(64), 1, bi.h1 + sum_w]
template <int L, bool IS_USER>
__global__ __launch_bounds__(256)
void fm_rows_kernel(const float* __restrict__ emb,   // [V, 64]
                    const float* __restrict__ w,     // [V]
                    const float* __restrict__ gbias, // [1] (users only)
                    const float* __restrict__ h1,    // [64]
                    const float* __restrict__ h2,    // [64] (users only, tail copy)
                    const int*   __restrict__ idx,   // [N, L]
                    float*       __restrict__ out,   // row base for this table
                    int n_rows)
{
    const int lane = threadIdx.x & 31;
    const int row  = (blockIdx.x * blockDim.x + threadIdx.x) >> 5;

    // h2 tail copy (users launch only, one block does it)
    if (IS_USER && blockIdx.x == 0 && threadIdx.x < D_DIM) {
        // out points at P base == d_out base for the user launch
        out[(size_t)(N_USERS + N_ITEMS) * OUT_W + threadIdx.x] = h2[threadIdx.x];
    }

    if (row >= n_rows) return;

    const int* __restrict__ my_idx = idx + (size_t)row * L;

    // Preload indices into registers; broadcast via shuffle in the loop.
    int idx_lo = (lane < L)      ? my_idx[lane]      : 0;
    int idx_hi = (lane + 32 < L) ? my_idx[lane + 32] : 0;

    // w-gather partial (lane j handles features j and j+32)
    float wsum = 0.f;
    if (lane < L)      wsum += __ldg(&w[idx_lo]);
    if (lane + 32 < L) wsum += __ldg(&w[idx_hi]);

    float sx = 0.f, sy = 0.f, qx = 0.f, qy = 0.f;

    #pragma unroll
    for (int j = 0; j < L; ++j) {
        int src = (j < 32) ? idx_lo : idx_hi;
        int r   = __shfl_sync(0xffffffffu, src, j & 31);
        float2 g = *reinterpret_cast<const float2*>(emb + (size_t)r * D_DIM + 2 * lane);
        sx += g.x; sy += g.y;
        qx += g.x * g.x; qy += g.y * g.y;
    }

    // bi-interaction + dot with h1 (per-lane partial over 2 dims)
    float2 h = *reinterpret_cast<const float2*>(h1 + 2 * lane);
    float bi0 = 0.5f * (sx * sx - qx);
    float bi1 = 0.5f * (sy * sy - qy);
    float part = bi0 * h.x + bi1 * h.y + wsum;

    #pragma unroll
    for (int o = 16; o > 0; o >>= 1)
        part += __shfl_xor_sync(0xffffffffu, part, o);

    float* __restrict__ orow = out + (size_t)row * OUT_W;
    // row stride 66 f32 = 264 B: row*66 is even -> 8B-aligned float2 stores OK
    float2 sv; sv.x = sx; sv.y = sy;
    *reinterpret_cast<float2*>(orow + 2 * lane) = sv;

    if (lane == 0) {
        if (IS_USER) {
            orow[D_DIM]     = part + gbias[0];
            orow[D_DIM + 1] = 1.0f;
        } else {
            orow[D_DIM]     = 1.0f;
            orow[D_DIM + 1] = part;
        }
    }
}

extern "C" void kernel_launch(void* const* d_in, const int* in_sizes, int n_in,
                              void* d_out, int out_size)
{
    // metadata order:
    // 0 user_features_embeddings [100000,64] f32
    // 1 item_features_embeddings [100000,64] f32
    // 2 user_w [100000] f32
    // 3 item_w [100000] f32
    // 4 global_bias [1] f32
    // 5 h1 [64] f32
    // 6 h2 [64] f32
    // 7 user_idx [4096,50] i32
    // 8 item_idx [16384,20] i32
    const float* uemb  = (const float*)d_in[0];
    const float* iemb  = (const float*)d_in[1];
    const float* uw    = (const float*)d_in[2];
    const float* iw    = (const float*)d_in[3];
    const float* gbias = (const float*)d_in[4];
    const float* h1    = (const float*)d_in[5];
    const float* h2    = (const float*)d_in[6];
    const int*   uidx  = (const int*)d_in[7];
    const int*   iidx  = (const int*)d_in[8];

    float* out = (float*)d_out;
    float* q_base = out + (size_t)N_USERS * OUT_W;

    const int threads = 256;               // 8 warps / block
    const int warps_per_block = threads / 32;

    int ublocks = (N_USERS + warps_per_block - 1) / warps_per_block;   // 512
    int iblocks = (N_ITEMS + warps_per_block - 1) / warps_per_block;   // 2048

    fm_rows_kernel<L_U, true ><<<ublocks, threads>>>(uemb, uw, gbias, h1, h2, uidx, out,    N_USERS);
    fm_rows_kernel<L_I, false><<<iblocks, threads>>>(iemb, iw, gbias, h1, h2, iidx, q_base, N_ITEMS);
}

// round 3
// speedup vs baseline: 1.1015x; 1.1015x over previous
#include <cuda_runtime.h>
#include <cstddef>

#define D_DIM   64
#define N_USERS 4096
#define N_ITEMS 16384
#define L_U     50
#define L_I     20
#define OUT_W   (D_DIM + 2)   // 66
#define N_ROWS  (N_USERS + N_ITEMS)

// One warp computes one output row. Lane l owns columns 2l, 2l+1.
// Explicit register batching (B=10) to keep many gathers in flight.
template <int L, bool IS_USER>
__device__ __forceinline__
void do_row(const float* __restrict__ emb,
            const float* __restrict__ w,
            float                     bias,   // global_bias for users, 0 otherwise
            const float* __restrict__ h1,
            const int*   __restrict__ my_idx, // this row's L indices
            float*       __restrict__ orow,   // this row's 66-float output
            int lane)
{
    // Preload indices into registers; broadcast via shuffle.
    int idx_lo = (lane < L) ? my_idx[lane] : 0;
    int idx_hi = 0;
    if (L > 32) idx_hi = (lane + 32 < L) ? my_idx[lane + 32] : 0;

    // w-gather partial
    float wsum = 0.f;
    if (lane < L) wsum += __ldg(&w[idx_lo]);
    if (L > 32 && lane + 32 < L) wsum += __ldg(&w[idx_hi]);

    float sx = 0.f, sy = 0.f, qx = 0.f, qy = 0.f;

    constexpr int B = 10;  // gathers staged per batch (20 f32 regs in flight)
    #pragma unroll
    for (int j0 = 0; j0 < L; j0 += B) {
        float2 g[B];
        #pragma unroll
        for (int k = 0; k < B; ++k) {
            const int j = j0 + k;
            if (j < L) {
                int src = (L <= 32 || j < 32) ? idx_lo : idx_hi;
                int r   = __shfl_sync(0xffffffffu, src, j & 31);
                g[k] = *reinterpret_cast<const float2*>(emb + (size_t)r * D_DIM + 2 * lane);
            } else {
                g[k].x = 0.f; g[k].y = 0.f;
            }
        }
        #pragma unroll
        for (int k = 0; k < B; ++k) {
            sx += g[k].x; sy += g[k].y;
            qx += g[k].x * g[k].x; qy += g[k].y * g[k].y;
        }
    }

    float2 h = *reinterpret_cast<const float2*>(h1 + 2 * lane);
    float bi0 = 0.5f * (sx * sx - qx);
    float bi1 = 0.5f * (sy * sy - qy);
    float part = bi0 * h.x + bi1 * h.y + wsum;

    #pragma unroll
    for (int o = 16; o > 0; o >>= 1)
        part += __shfl_xor_sync(0xffffffffu, part, o);

    float2 sv; sv.x = sx; sv.y = sy;
    *reinterpret_cast<float2*>(orow + 2 * lane) = sv;

    if (lane == 0) {
        if (IS_USER) {
            orow[D_DIM]     = part + bias;
            orow[D_DIM + 1] = 1.0f;
        } else {
            orow[D_DIM]     = 1.0f;
            orow[D_DIM + 1] = part;
        }
    }
}

__global__ __launch_bounds__(256)
void fm_fused_kernel(const float* __restrict__ uemb,
                     const float* __restrict__ iemb,
                     const float* __restrict__ uw,
                     const float* __restrict__ iw,
                     const float* __restrict__ gbias,
                     const float* __restrict__ h1,
                     const float* __restrict__ h2,
                     const int*   __restrict__ uidx,
                     const int*   __restrict__ iidx,
                     float*       __restrict__ out)
{
    const int lane = threadIdx.x & 31;
    const int gw   = (blockIdx.x * blockDim.x + threadIdx.x) >> 5;  // global warp id

    // h2 tail copy (one block)
    if (blockIdx.x == 0 && threadIdx.x < D_DIM) {
        out[(size_t)N_ROWS * OUT_W + threadIdx.x] = h2[threadIdx.x];
    }

    if (gw < N_USERS) {
        const int row = gw;
        do_row<L_U, true>(uemb, uw, gbias[0], h1,
                          uidx + (size_t)row * L_U,
                          out + (size_t)row * OUT_W, lane);
    } else if (gw < N_ROWS) {
        const int row = gw - N_USERS;
        do_row<L_I, false>(iemb, iw, 0.f, h1,
                           iidx + (size_t)row * L_I,
                           out + (size_t)(N_USERS + row) * OUT_W, lane);
    }
}

extern "C" void kernel_launch(void* const* d_in, const int* in_sizes, int n_in,
                              void* d_out, int out_size)
{
    const float* uemb  = (const float*)d_in[0];
    const float* iemb  = (const float*)d_in[1];
    const float* uw    = (const float*)d_in[2];
    const float* iw    = (const float*)d_in[3];
    const float* gbias = (const float*)d_in[4];
    const float* h1    = (const float*)d_in[5];
    const float* h2    = (const float*)d_in[6];
    const int*   uidx  = (const int*)d_in[7];
    const int*   iidx  = (const int*)d_in[8];

    float* out = (float*)d_out;

    const int threads = 256;                 // 8 warps/block
    const int warps_per_block = threads / 32;
    const int blocks = (N_ROWS + warps_per_block - 1) / warps_per_block;  // 2560

    fm_fused_kernel<<<blocks, threads>>>(uemb, iemb, uw, iw, gbias, h1, h2,
                                         uidx, iidx, out);
}